// round 7
// baseline (speedup 1.0000x reference)
#include <cuda_runtime.h>

// ---------------------------------------------------------------------------
// GAT 2-layer forward on GB300. CSR-by-dst, two-pass warp-per-dst softmax
// aggregation (lane-parallel exp precompute, MLP-4 gathers), double-buffered
// pipelined SGEMM. edge_index is int32.
// ---------------------------------------------------------------------------

#define NMAX 50000
#define EMAX 1600000
#define ETOT (EMAX + NMAX)
#define CAP1 96
#define CAP2 128

__device__ __align__(16) float g_h1[NMAX * 128];
__device__ __align__(16) float g_out1[NMAX * 128];
__device__ __align__(16) float g_h2[NMAX * 64];
__device__ __align__(16) float g_as1[NMAX * 4];
__device__ __align__(16) float g_ad1[NMAX * 4];
__device__ float g_as2[NMAX];
__device__ float g_ad2[NMAX];
__device__ int   g_cnt[NMAX];
__device__ int   g_off[NMAX + 1];
__device__ int   g_csr[ETOT];

// ---------------------------------------------------------------------------
// CSR construction
// ---------------------------------------------------------------------------

__global__ void k_init(int n) {
    int i = blockIdx.x * blockDim.x + threadIdx.x;
    if (i < n) g_cnt[i] = 1;
}

__global__ void k_count(const int* __restrict__ dst, int e, int n) {
    int i = blockIdx.x * blockDim.x + threadIdx.x;
    if (i < e) {
        int d = dst[i];
        if ((unsigned)d < (unsigned)n) atomicAdd(&g_cnt[d], 1);
    }
}

__global__ void k_scan(int n) {
    __shared__ int warpsum[32];
    __shared__ int s_running;
    int tid = threadIdx.x, lane = tid & 31, wid = tid >> 5;
    if (tid == 0) s_running = 0;
    __syncthreads();
    for (int base = 0; base < n; base += 1024) {
        int i = base + tid;
        int v = (i < n) ? g_cnt[i] : 0;
        int x = v;
#pragma unroll
        for (int o = 1; o < 32; o <<= 1) {
            int t = __shfl_up_sync(0xffffffffu, x, o);
            if (lane >= o) x += t;
        }
        if (lane == 31) warpsum[wid] = x;
        __syncthreads();
        if (wid == 0) {
            int y = warpsum[lane];
#pragma unroll
            for (int o = 1; o < 32; o <<= 1) {
                int t = __shfl_up_sync(0xffffffffu, y, o);
                if (lane >= o) y += t;
            }
            warpsum[lane] = y;
        }
        __syncthreads();
        int warpoff = (wid == 0) ? 0 : warpsum[wid - 1];
        if (i < n) g_off[i] = s_running + warpoff + x - v;
        int total = warpsum[31];
        __syncthreads();
        if (tid == 0) s_running += total;
    }
    __syncthreads();
    if (threadIdx.x == 0) g_off[n] = s_running;
}

__global__ void k_selfloop(int n) {
    int i = blockIdx.x * blockDim.x + threadIdx.x;
    if (i < n) {
        int c = g_off[i];
        g_csr[c] = i;
        g_cnt[i] = c + 1;
    }
}

__global__ void k_fill(const int* __restrict__ src,
                       const int* __restrict__ dst, int e, int n) {
    int i = blockIdx.x * blockDim.x + threadIdx.x;
    if (i < e) {
        int d = dst[i];
        if ((unsigned)d < (unsigned)n) {
            int pos = atomicAdd(&g_cnt[d], 1);
            if (pos < ETOT) g_csr[pos] = src[i];
        }
    }
}

// ---------------------------------------------------------------------------
// SGEMM: C[M,BN] = A[M,128] @ B[128,BN]. Double-buffered smem, pipelined
// register fragments. BM=128, BK=8, 256 threads, TM=8 x TN tile.
// ---------------------------------------------------------------------------

template <int BN, int TN>
__global__ void __launch_bounds__(256) k_sgemm(const float* __restrict__ A,
                                               const float* __restrict__ B,
                                               float* __restrict__ C, int M) {
    constexpr int BM = 128, BK = 8, TM = 8;
    constexpr int NSTAGE = 128 / BK;  // 16
    __shared__ float As[2][BK][BM];
    __shared__ float Bs[2][BK][BN];
    const int tid = threadIdx.x;
    const int tx = tid % (BN / TN);
    const int ty = tid / (BN / TN);
    const int rowBase = blockIdx.x * BM;

    // A-load mapping: 256 float4 per stage -> 1/thread.
    const int ar = tid >> 1;
    const int ak = (tid & 1) * 4;
    const int arow = rowBase + ar;
    const bool aok = arow < M;
    const float* aptr = A + (long)arow * 128 + ak;
    // B-load mapping: BK*BN/4 float4 per stage.
    constexpr int bslots = BK * BN / 4;
    const int bk = tid / (BN / 4);
    const int bc = (tid % (BN / 4)) * 4;
    const bool bok = tid < bslots;
    const float* bptr = B + bk * BN + bc;

    // Prologue: stage 0.
    {
        float4 av = make_float4(0.f, 0.f, 0.f, 0.f);
        if (aok) av = *(const float4*)aptr;
        As[0][ak + 0][ar] = av.x;
        As[0][ak + 1][ar] = av.y;
        As[0][ak + 2][ar] = av.z;
        As[0][ak + 3][ar] = av.w;
        if (bok) *(float4*)&Bs[0][bk][bc] = *(const float4*)bptr;
    }
    __syncthreads();

    float acc[TM][TN];
#pragma unroll
    for (int i = 0; i < TM; i++)
#pragma unroll
        for (int j = 0; j < TN; j++) acc[i][j] = 0.f;

#pragma unroll 1
    for (int s = 0; s < NSTAGE; s++) {
        const int buf = s & 1;
        // Prefetch next stage from gmem (overlaps with compute below).
        float4 na = make_float4(0.f, 0.f, 0.f, 0.f), nb = na;
        if (s + 1 < NSTAGE) {
            if (aok) na = *(const float4*)(aptr + (s + 1) * BK);
            if (bok) nb = *(const float4*)(bptr + (s + 1) * BK * BN);
        }
        // Compute stage s with register-fragment double buffering.
        float afr[2][TM], bfr[2][TN];
#pragma unroll
        for (int i = 0; i < TM; i++) afr[0][i] = As[buf][0][ty * TM + i];
#pragma unroll
        for (int j = 0; j < TN; j++) bfr[0][j] = Bs[buf][0][tx * TN + j];
#pragma unroll
        for (int k = 0; k < BK; k++) {
            const int cur = k & 1, nxt = cur ^ 1;
            if (k + 1 < BK) {
#pragma unroll
                for (int i = 0; i < TM; i++) afr[nxt][i] = As[buf][k + 1][ty * TM + i];
#pragma unroll
                for (int j = 0; j < TN; j++) bfr[nxt][j] = Bs[buf][k + 1][tx * TN + j];
            }
#pragma unroll
            for (int i = 0; i < TM; i++)
#pragma unroll
                for (int j = 0; j < TN; j++)
                    acc[i][j] = fmaf(afr[cur][i], bfr[cur][j], acc[i][j]);
        }
        if (s + 1 < NSTAGE) {
            const int obuf = buf ^ 1;
            As[obuf][ak + 0][ar] = na.x;
            As[obuf][ak + 1][ar] = na.y;
            As[obuf][ak + 2][ar] = na.z;
            As[obuf][ak + 3][ar] = na.w;
            if (bok) *(float4*)&Bs[obuf][bk][bc] = nb;
            __syncthreads();
        }
    }

#pragma unroll
    for (int i = 0; i < TM; i++) {
        int grow = rowBase + ty * TM + i;
        if (grow < M) {
#pragma unroll
            for (int j = 0; j < TN; j += 4) {
                float4 v = make_float4(acc[i][j], acc[i][j + 1], acc[i][j + 2],
                                       acc[i][j + 3]);
                *(float4*)(C + (long)grow * BN + tx * TN + j) = v;
            }
        }
    }
}

// ---------------------------------------------------------------------------
// Attention coefficients
// ---------------------------------------------------------------------------

__global__ void k_att1(const float* __restrict__ h,
                       const float* __restrict__ att_s,
                       const float* __restrict__ att_d, int n) {
    int w = (blockIdx.x * blockDim.x + threadIdx.x) >> 5;
    if (w >= n) return;
    int lane = threadIdx.x & 31;
    float4 hv = *(const float4*)(h + (long)w * 128 + lane * 4);
    float4 s4 = *(const float4*)(att_s + lane * 4);
    float4 d4 = *(const float4*)(att_d + lane * 4);
    float vs = hv.x * s4.x + hv.y * s4.y + hv.z * s4.z + hv.w * s4.w;
    float vd = hv.x * d4.x + hv.y * d4.y + hv.z * d4.z + hv.w * d4.w;
    vs += __shfl_xor_sync(0xffffffffu, vs, 1);
    vd += __shfl_xor_sync(0xffffffffu, vd, 1);
    vs += __shfl_xor_sync(0xffffffffu, vs, 2);
    vd += __shfl_xor_sync(0xffffffffu, vd, 2);
    vs += __shfl_xor_sync(0xffffffffu, vs, 4);
    vd += __shfl_xor_sync(0xffffffffu, vd, 4);
    if ((lane & 7) == 0) {
        g_as1[w * 4 + (lane >> 3)] = vs;
        g_ad1[w * 4 + (lane >> 3)] = vd;
    }
}

__global__ void k_att2(const float* __restrict__ h,
                       const float* __restrict__ att_s,
                       const float* __restrict__ att_d, int n) {
    int w = (blockIdx.x * blockDim.x + threadIdx.x) >> 5;
    if (w >= n) return;
    int lane = threadIdx.x & 31;
    float2 hv = *(const float2*)(h + (long)w * 64 + lane * 2);
    float2 s2 = *(const float2*)(att_s + lane * 2);
    float2 d2 = *(const float2*)(att_d + lane * 2);
    float vs = hv.x * s2.x + hv.y * s2.y;
    float vd = hv.x * d2.x + hv.y * d2.y;
#pragma unroll
    for (int o = 16; o >= 1; o >>= 1) {
        vs += __shfl_xor_sync(0xffffffffu, vs, o);
        vd += __shfl_xor_sync(0xffffffffu, vd, o);
    }
    if (lane == 0) {
        g_as2[w] = vs;
        g_ad2[w] = vd;
    }
}

// ---------------------------------------------------------------------------
// Aggregation. Pass A: lanes parallel, e->smem, warp max. Pass A2: lanes
// parallel exp + partial sums (p overwrites e in smem). Pass B: unroll-4
// gather + FMA only (MLP=4 on LDG.128).
// ---------------------------------------------------------------------------

__global__ void __launch_bounds__(256) k_agg1(const float* __restrict__ h,
                                              const float* __restrict__ bias,
                                              float* __restrict__ out, int n) {
    __shared__ __align__(16) float sE[8][CAP1 * 4];
    __shared__ int sS[8][CAP1];
    int w = (blockIdx.x * blockDim.x + threadIdx.x) >> 5;
    if (w >= n) return;
    int wip = threadIdx.x >> 5;
    int lane = threadIdx.x & 31;
    int head = lane >> 3;
    float4 ad4 = *(const float4*)(g_ad1 + w * 4);
    int beg = g_off[w];
    int len = g_off[w + 1] - beg;

    float s = 0.f;
    float4 acc = make_float4(0.f, 0.f, 0.f, 0.f);

    if (len <= CAP1) {
        // ---- pass A ----
        float4 mx = make_float4(-1e30f, -1e30f, -1e30f, -1e30f);
        for (int j = lane; j < len; j += 32) {
            int src = g_csr[beg + j];
            sS[wip][j] = src;
            float4 a = *(const float4*)(g_as1 + src * 4);
            float4 e;
            e.x = a.x + ad4.x; e.x = e.x > 0.f ? e.x : 0.2f * e.x;
            e.y = a.y + ad4.y; e.y = e.y > 0.f ? e.y : 0.2f * e.y;
            e.z = a.z + ad4.z; e.z = e.z > 0.f ? e.z : 0.2f * e.z;
            e.w = a.w + ad4.w; e.w = e.w > 0.f ? e.w : 0.2f * e.w;
            ((float4*)sE[wip])[j] = e;
            mx.x = fmaxf(mx.x, e.x);
            mx.y = fmaxf(mx.y, e.y);
            mx.z = fmaxf(mx.z, e.z);
            mx.w = fmaxf(mx.w, e.w);
        }
#pragma unroll
        for (int o = 16; o >= 1; o >>= 1) {
            mx.x = fmaxf(mx.x, __shfl_xor_sync(0xffffffffu, mx.x, o));
            mx.y = fmaxf(mx.y, __shfl_xor_sync(0xffffffffu, mx.y, o));
            mx.z = fmaxf(mx.z, __shfl_xor_sync(0xffffffffu, mx.z, o));
            mx.w = fmaxf(mx.w, __shfl_xor_sync(0xffffffffu, mx.w, o));
        }
        // ---- pass A2: p = exp(e - m), partial sums, overwrite smem ----
        float4 sp = make_float4(0.f, 0.f, 0.f, 0.f);
        for (int j = lane; j < len; j += 32) {
            float4 e = ((float4*)sE[wip])[j];
            float4 p;
            p.x = __expf(e.x - mx.x);
            p.y = __expf(e.y - mx.y);
            p.z = __expf(e.z - mx.z);
            p.w = __expf(e.w - mx.w);
            ((float4*)sE[wip])[j] = p;
            sp.x += p.x; sp.y += p.y; sp.z += p.z; sp.w += p.w;
        }
#pragma unroll
        for (int o = 16; o >= 1; o >>= 1) {
            sp.x += __shfl_xor_sync(0xffffffffu, sp.x, o);
            sp.y += __shfl_xor_sync(0xffffffffu, sp.y, o);
            sp.z += __shfl_xor_sync(0xffffffffu, sp.z, o);
            sp.w += __shfl_xor_sync(0xffffffffu, sp.w, o);
        }
        s = head == 0 ? sp.x : head == 1 ? sp.y : head == 2 ? sp.z : sp.w;
        __syncwarp();
        // ---- pass B: gather + FMA, unroll 4 ----
        const float* hl = h + lane * 4;
        int j = 0;
        for (; j + 4 <= len; j += 4) {
            int s0 = sS[wip][j], s1 = sS[wip][j + 1];
            int s2 = sS[wip][j + 2], s3 = sS[wip][j + 3];
            float p0 = sE[wip][(j + 0) * 4 + head];
            float p1 = sE[wip][(j + 1) * 4 + head];
            float p2 = sE[wip][(j + 2) * 4 + head];
            float p3 = sE[wip][(j + 3) * 4 + head];
            float4 h0 = *(const float4*)(hl + (long)s0 * 128);
            float4 h1 = *(const float4*)(hl + (long)s1 * 128);
            float4 h2 = *(const float4*)(hl + (long)s2 * 128);
            float4 h3 = *(const float4*)(hl + (long)s3 * 128);
            acc.x += p0 * h0.x + p1 * h1.x + p2 * h2.x + p3 * h3.x;
            acc.y += p0 * h0.y + p1 * h1.y + p2 * h2.y + p3 * h3.y;
            acc.z += p0 * h0.z + p1 * h1.z + p2 * h2.z + p3 * h3.z;
            acc.w += p0 * h0.w + p1 * h1.w + p2 * h2.w + p3 * h3.w;
        }
        for (; j < len; j++) {
            int s0 = sS[wip][j];
            float p0 = sE[wip][j * 4 + head];
            float4 h0 = *(const float4*)(hl + (long)s0 * 128);
            acc.x += p0 * h0.x;
            acc.y += p0 * h0.y;
            acc.z += p0 * h0.z;
            acc.w += p0 * h0.w;
        }
    } else {
        // fallback: online softmax
        float ad = head == 0 ? ad4.x : head == 1 ? ad4.y : head == 2 ? ad4.z : ad4.w;
        float m = -1e30f;
        for (int i = beg; i < beg + len; ++i) {
            int src = g_csr[i];
            float e = g_as1[src * 4 + head] + ad;
            e = e > 0.f ? e : 0.2f * e;
            float4 hv = *(const float4*)(h + (long)src * 128 + lane * 4);
            float mn = fmaxf(m, e);
            float sc = __expf(m - mn);
            float p = __expf(e - mn);
            s = s * sc + p;
            acc.x = acc.x * sc + p * hv.x;
            acc.y = acc.y * sc + p * hv.y;
            acc.z = acc.z * sc + p * hv.z;
            acc.w = acc.w * sc + p * hv.w;
            m = mn;
        }
    }
    float inv = 1.f / (s + 1e-16f);
    float4 b = *(const float4*)(bias + lane * 4);
    float4 o;
    o.x = acc.x * inv + b.x;
    o.y = acc.y * inv + b.y;
    o.z = acc.z * inv + b.z;
    o.w = acc.w * inv + b.w;
    o.x = o.x > 0.f ? o.x : (__expf(o.x) - 1.f);
    o.y = o.y > 0.f ? o.y : (__expf(o.y) - 1.f);
    o.z = o.z > 0.f ? o.z : (__expf(o.z) - 1.f);
    o.w = o.w > 0.f ? o.w : (__expf(o.w) - 1.f);
    *(float4*)(out + (long)w * 128 + lane * 4) = o;
}

__global__ void __launch_bounds__(256) k_agg2(const float* __restrict__ h,
                                              const float* __restrict__ bias,
                                              float* __restrict__ out, int n) {
    __shared__ float sE[8][CAP2];
    __shared__ int sS[8][CAP2];
    int w = (blockIdx.x * blockDim.x + threadIdx.x) >> 5;
    if (w >= n) return;
    int wip = threadIdx.x >> 5;
    int lane = threadIdx.x & 31;
    float ad = g_ad2[w];
    int beg = g_off[w];
    int len = g_off[w + 1] - beg;

    float s = 0.f;
    float2 acc = make_float2(0.f, 0.f);

    if (len <= CAP2) {
        float mx = -1e30f;
        for (int j = lane; j < len; j += 32) {
            int src = g_csr[beg + j];
            sS[wip][j] = src;
            float e = g_as2[src] + ad;
            e = e > 0.f ? e : 0.2f * e;
            sE[wip][j] = e;
            mx = fmaxf(mx, e);
        }
#pragma unroll
        for (int o = 16; o >= 1; o >>= 1)
            mx = fmaxf(mx, __shfl_xor_sync(0xffffffffu, mx, o));
        float sp = 0.f;
        for (int j = lane; j < len; j += 32) {
            float p = __expf(sE[wip][j] - mx);
            sE[wip][j] = p;
            sp += p;
        }
#pragma unroll
        for (int o = 16; o >= 1; o >>= 1)
            sp += __shfl_xor_sync(0xffffffffu, sp, o);
        s = sp;
        __syncwarp();
        const float* hl = h + lane * 2;
        int j = 0;
        for (; j + 4 <= len; j += 4) {
            int s0 = sS[wip][j], s1 = sS[wip][j + 1];
            int s2 = sS[wip][j + 2], s3 = sS[wip][j + 3];
            float p0 = sE[wip][j], p1 = sE[wip][j + 1];
            float p2 = sE[wip][j + 2], p3 = sE[wip][j + 3];
            float2 h0 = *(const float2*)(hl + (long)s0 * 64);
            float2 h1 = *(const float2*)(hl + (long)s1 * 64);
            float2 h2 = *(const float2*)(hl + (long)s2 * 64);
            float2 h3 = *(const float2*)(hl + (long)s3 * 64);
            acc.x += p0 * h0.x + p1 * h1.x + p2 * h2.x + p3 * h3.x;
            acc.y += p0 * h0.y + p1 * h1.y + p2 * h2.y + p3 * h3.y;
        }
        for (; j < len; j++) {
            int s0 = sS[wip][j];
            float p0 = sE[wip][j];
            float2 h0 = *(const float2*)(hl + (long)s0 * 64);
            acc.x += p0 * h0.x;
            acc.y += p0 * h0.y;
        }
    } else {
        float m = -1e30f;
        for (int i = beg; i < beg + len; ++i) {
            int src = g_csr[i];
            float e = g_as2[src] + ad;
            e = e > 0.f ? e : 0.2f * e;
            float2 hv = *(const float2*)(h + (long)src * 64 + lane * 2);
            float mn = fmaxf(m, e);
            float sc = __expf(m - mn);
            float p = __expf(e - mn);
            s = s * sc + p;
            acc.x = acc.x * sc + p * hv.x;
            acc.y = acc.y * sc + p * hv.y;
            m = mn;
        }
    }
    float inv = 1.f / (s + 1e-16f);
    float2 b = *(const float2*)(bias + lane * 2);
    float2 o;
    o.x = acc.x * inv + b.x;
    o.y = acc.y * inv + b.y;
    *(float2*)(out + (long)w * 64 + lane * 2) = o;
}

// ---------------------------------------------------------------------------

extern "C" void kernel_launch(void* const* d_in, const int* in_sizes, int n_in,
                              void* d_out, int out_size) {
    const float* x = (const float*)d_in[0];
    const int* ei = (const int*)d_in[1];   // int32
    const float* W1 = (const float*)d_in[2];
    const float* att_s1 = (const float*)d_in[3];
    const float* att_d1 = (const float*)d_in[4];
    const float* b1 = (const float*)d_in[5];
    const float* W2 = (const float*)d_in[6];
    const float* att_s2 = (const float*)d_in[7];
    const float* att_d2 = (const float*)d_in[8];
    const float* b2 = (const float*)d_in[9];
    float* out = (float*)d_out;

    const int N = in_sizes[0] / 128;
    const int E = in_sizes[1] / 2;
    const int* src = ei;
    const int* dst = ei + E;

    const int warpBlocks = (N * 32 + 255) / 256;

    // sgemm1 kept at my 4th launch (that's the slot ncu profiles).
    k_init<<<(N + 255) / 256, 256>>>(N);                       // 1
    k_count<<<(E + 255) / 256, 256>>>(dst, E, N);              // 2
    k_scan<<<1, 1024>>>(N);                                    // 3
    k_sgemm<128, 8><<<(N + 127) / 128, 256>>>(x, W1, g_h1, N); // 4
    k_selfloop<<<(N + 255) / 256, 256>>>(N);                   // 5
    k_fill<<<(E + 255) / 256, 256>>>(src, dst, E, N);          // 6
    k_att1<<<warpBlocks, 256>>>(g_h1, att_s1, att_d1, N);      // 7
    k_agg1<<<warpBlocks, 256>>>(g_h1, b1, g_out1, N);          // 8
    k_sgemm<64, 4><<<(N + 127) / 128, 256>>>(g_out1, W2, g_h2, N); // 9
    k_att2<<<warpBlocks, 256>>>(g_h2, att_s2, att_d2, N);      // 10
    k_agg2<<<warpBlocks, 256>>>(g_h2, b2, out, N);             // 11
}

// round 9
// speedup vs baseline: 1.1548x; 1.1548x over previous
#include <cuda_runtime.h>

// ---------------------------------------------------------------------------
// GAT 2-layer forward on GB300. CSR-by-dst build, warp-per-dst two-pass
// softmax aggregation (R7-proven kernels), SGEMM with float4 smem fragments.
// edge_index is int32.
// ---------------------------------------------------------------------------

#define NMAX 50000
#define EMAX 1600000
#define ETOT (EMAX + NMAX)
#define CAP1 96
#define CAP2 128

__device__ __align__(16) float g_h1[NMAX * 128];
__device__ __align__(16) float g_out1[NMAX * 128];
__device__ __align__(16) float g_h2[NMAX * 64];
__device__ __align__(16) float g_as1[NMAX * 4];
__device__ __align__(16) float g_ad1[NMAX * 4];
__device__ float g_as2[NMAX];
__device__ float g_ad2[NMAX];
__device__ int   g_cnt[NMAX];     // statically zero; reset to 0 by k_agg2 tail
__device__ int   g_cur[NMAX];     // fill cursors
__device__ int   g_off[NMAX + 1];
__device__ int   g_csr[ETOT];

// ---------------------------------------------------------------------------
// CSR construction. g_cnt starts at zero (static init / reset by k_agg2),
// scan adds +1 per row for the self-loop.
// ---------------------------------------------------------------------------

__global__ void k_count(const int* __restrict__ dst, int e, int n) {
    int i = blockIdx.x * blockDim.x + threadIdx.x;
    if (i < e) {
        int d = dst[i];
        if ((unsigned)d < (unsigned)n) atomicAdd(&g_cnt[d], 1);
    }
}

// Single-block shuffle-based exclusive scan of (g_cnt[i] + 1).
__global__ void k_scan(int n) {
    __shared__ int warpsum[32];
    __shared__ int s_running;
    int tid = threadIdx.x, lane = tid & 31, wid = tid >> 5;
    if (tid == 0) s_running = 0;
    __syncthreads();
    for (int base = 0; base < n; base += 1024) {
        int i = base + tid;
        int v = (i < n) ? g_cnt[i] + 1 : 0;   // +1 = self-loop
        int x = v;
#pragma unroll
        for (int o = 1; o < 32; o <<= 1) {
            int t = __shfl_up_sync(0xffffffffu, x, o);
            if (lane >= o) x += t;
        }
        if (lane == 31) warpsum[wid] = x;
        __syncthreads();
        if (wid == 0) {
            int y = warpsum[lane];
#pragma unroll
            for (int o = 1; o < 32; o <<= 1) {
                int t = __shfl_up_sync(0xffffffffu, y, o);
                if (lane >= o) y += t;
            }
            warpsum[lane] = y;
        }
        __syncthreads();
        int warpoff = (wid == 0) ? 0 : warpsum[wid - 1];
        if (i < n) g_off[i] = s_running + warpoff + x - v;
        int total = warpsum[31];
        __syncthreads();
        if (tid == 0) s_running += total;
    }
    __syncthreads();
    if (threadIdx.x == 0) g_off[n] = s_running;
}

__global__ void k_selfloop(int n) {
    int i = blockIdx.x * blockDim.x + threadIdx.x;
    if (i < n) {
        int c = g_off[i];
        g_csr[c] = i;        // self loop first in row
        g_cur[i] = c + 1;    // fill cursor
    }
}

__global__ void k_fill(const int* __restrict__ src,
                       const int* __restrict__ dst, int e, int n) {
    int i = blockIdx.x * blockDim.x + threadIdx.x;
    if (i < e) {
        int d = dst[i];
        if ((unsigned)d < (unsigned)n) {
            int pos = atomicAdd(&g_cur[d], 1);
            if (pos < ETOT) g_csr[pos] = src[i];
        }
    }
}

// ---------------------------------------------------------------------------
// SGEMM: C[M,BN] = A[M,128] @ B[128,BN]. BM=128, BK=16, 256 threads,
// TM=8 x TN register tile, float4 (LDS.128) smem fragment loads.
// ---------------------------------------------------------------------------

template <int BN, int TN>
__global__ void __launch_bounds__(256) k_sgemm(const float* __restrict__ A,
                                               const float* __restrict__ B,
                                               float* __restrict__ C, int M) {
    constexpr int BM = 128, BK = 16, TM = 8;
    __shared__ float As[BK][BM];
    __shared__ float Bs[BK][BN];
    const int tid = threadIdx.x;
    const int tx = tid % (BN / TN);   // 16
    const int ty = tid / (BN / TN);   // 0..15
    const int rowBase = blockIdx.x * BM;

    float acc[TM][TN];
#pragma unroll
    for (int i = 0; i < TM; i++)
#pragma unroll
        for (int j = 0; j < TN; j++) acc[i][j] = 0.f;

    for (int kk = 0; kk < 128; kk += BK) {
        // A tile: 128 rows x 16 k = 512 float4 -> 2 per thread.
        {
            int r = tid >> 1;
            int k4 = (tid & 1) * 4;
            int grow = rowBase + r;
#pragma unroll
            for (int half = 0; half < 2; half++) {
                float4 v = make_float4(0.f, 0.f, 0.f, 0.f);
                if (grow < M)
                    v = *(const float4*)(A + (long)grow * 128 + kk + half * 8 + k4);
                As[half * 8 + k4 + 0][r] = v.x;
                As[half * 8 + k4 + 1][r] = v.y;
                As[half * 8 + k4 + 2][r] = v.z;
                As[half * 8 + k4 + 3][r] = v.w;
            }
        }
        // B tile.
        {
            constexpr int slots = BK * BN / 4;
#pragma unroll
            for (int s = tid; s < slots; s += 256) {
                int k = s / (BN / 4);
                int c4 = (s % (BN / 4)) * 4;
                *(float4*)&Bs[k][c4] = *(const float4*)(B + (kk + k) * BN + c4);
            }
        }
        __syncthreads();
#pragma unroll
        for (int k = 0; k < BK; k++) {
            // float4 fragment loads (LDS.128).
            float a[TM], b[TN];
            float4 a0 = *(const float4*)&As[k][ty * TM];
            float4 a1 = *(const float4*)&As[k][ty * TM + 4];
            a[0] = a0.x; a[1] = a0.y; a[2] = a0.z; a[3] = a0.w;
            a[4] = a1.x; a[5] = a1.y; a[6] = a1.z; a[7] = a1.w;
            float4 b0 = *(const float4*)&Bs[k][tx * TN];
            b[0] = b0.x; b[1] = b0.y; b[2] = b0.z; b[3] = b0.w;
            if (TN == 8) {
                float4 b1 = *(const float4*)&Bs[k][tx * TN + 4];
                b[4] = b1.x; b[5] = b1.y; b[6] = b1.z; b[7] = b1.w;
            }
#pragma unroll
            for (int i = 0; i < TM; i++)
#pragma unroll
                for (int j = 0; j < TN; j++) acc[i][j] = fmaf(a[i], b[j], acc[i][j]);
        }
        __syncthreads();
    }
#pragma unroll
    for (int i = 0; i < TM; i++) {
        int grow = rowBase + ty * TM + i;
        if (grow < M) {
#pragma unroll
            for (int j = 0; j < TN; j += 4) {
                float4 v = make_float4(acc[i][j], acc[i][j + 1], acc[i][j + 2],
                                       acc[i][j + 3]);
                *(float4*)(C + (long)grow * BN + tx * TN + j) = v;
            }
        }
    }
}

// ---------------------------------------------------------------------------
// Attention coefficients (R7-proven).
// ---------------------------------------------------------------------------

__global__ void k_att1(const float* __restrict__ h,
                       const float* __restrict__ att_s,
                       const float* __restrict__ att_d, int n) {
    int w = (blockIdx.x * blockDim.x + threadIdx.x) >> 5;
    if (w >= n) return;
    int lane = threadIdx.x & 31;
    float4 hv = *(const float4*)(h + (long)w * 128 + lane * 4);
    float4 s4 = *(const float4*)(att_s + lane * 4);
    float4 d4 = *(const float4*)(att_d + lane * 4);
    float vs = hv.x * s4.x + hv.y * s4.y + hv.z * s4.z + hv.w * s4.w;
    float vd = hv.x * d4.x + hv.y * d4.y + hv.z * d4.z + hv.w * d4.w;
    vs += __shfl_xor_sync(0xffffffffu, vs, 1);
    vd += __shfl_xor_sync(0xffffffffu, vd, 1);
    vs += __shfl_xor_sync(0xffffffffu, vs, 2);
    vd += __shfl_xor_sync(0xffffffffu, vd, 2);
    vs += __shfl_xor_sync(0xffffffffu, vs, 4);
    vd += __shfl_xor_sync(0xffffffffu, vd, 4);
    if ((lane & 7) == 0) {
        g_as1[w * 4 + (lane >> 3)] = vs;
        g_ad1[w * 4 + (lane >> 3)] = vd;
    }
}

__global__ void k_att2(const float* __restrict__ h,
                       const float* __restrict__ att_s,
                       const float* __restrict__ att_d, int n) {
    int w = (blockIdx.x * blockDim.x + threadIdx.x) >> 5;
    if (w >= n) return;
    int lane = threadIdx.x & 31;
    float2 hv = *(const float2*)(h + (long)w * 64 + lane * 2);
    float2 s2 = *(const float2*)(att_s + lane * 2);
    float2 d2 = *(const float2*)(att_d + lane * 2);
    float vs = hv.x * s2.x + hv.y * s2.y;
    float vd = hv.x * d2.x + hv.y * d2.y;
#pragma unroll
    for (int o = 16; o >= 1; o >>= 1) {
        vs += __shfl_xor_sync(0xffffffffu, vs, o);
        vd += __shfl_xor_sync(0xffffffffu, vd, o);
    }
    if (lane == 0) {
        g_as2[w] = vs;
        g_ad2[w] = vd;
    }
}

// ---------------------------------------------------------------------------
// Aggregation (R7-proven two-pass).
// ---------------------------------------------------------------------------

__global__ void __launch_bounds__(256) k_agg1(const float* __restrict__ h,
                                              const float* __restrict__ bias,
                                              float* __restrict__ out, int n) {
    __shared__ __align__(16) float sE[8][CAP1 * 4];
    __shared__ int sS[8][CAP1];
    int w = (blockIdx.x * blockDim.x + threadIdx.x) >> 5;
    if (w >= n) return;
    int wip = threadIdx.x >> 5;
    int lane = threadIdx.x & 31;
    int head = lane >> 3;
    float4 ad4 = *(const float4*)(g_ad1 + w * 4);
    int beg = g_off[w];
    int len = g_off[w + 1] - beg;

    float s = 0.f;
    float4 acc = make_float4(0.f, 0.f, 0.f, 0.f);

    if (len <= CAP1) {
        float4 mx = make_float4(-1e30f, -1e30f, -1e30f, -1e30f);
        for (int j = lane; j < len; j += 32) {
            int src = g_csr[beg + j];
            sS[wip][j] = src;
            float4 a = *(const float4*)(g_as1 + src * 4);
            float4 e;
            e.x = a.x + ad4.x; e.x = e.x > 0.f ? e.x : 0.2f * e.x;
            e.y = a.y + ad4.y; e.y = e.y > 0.f ? e.y : 0.2f * e.y;
            e.z = a.z + ad4.z; e.z = e.z > 0.f ? e.z : 0.2f * e.z;
            e.w = a.w + ad4.w; e.w = e.w > 0.f ? e.w : 0.2f * e.w;
            ((float4*)sE[wip])[j] = e;
            mx.x = fmaxf(mx.x, e.x);
            mx.y = fmaxf(mx.y, e.y);
            mx.z = fmaxf(mx.z, e.z);
            mx.w = fmaxf(mx.w, e.w);
        }
#pragma unroll
        for (int o = 16; o >= 1; o >>= 1) {
            mx.x = fmaxf(mx.x, __shfl_xor_sync(0xffffffffu, mx.x, o));
            mx.y = fmaxf(mx.y, __shfl_xor_sync(0xffffffffu, mx.y, o));
            mx.z = fmaxf(mx.z, __shfl_xor_sync(0xffffffffu, mx.z, o));
            mx.w = fmaxf(mx.w, __shfl_xor_sync(0xffffffffu, mx.w, o));
        }
        float4 sp = make_float4(0.f, 0.f, 0.f, 0.f);
        for (int j = lane; j < len; j += 32) {
            float4 e = ((float4*)sE[wip])[j];
            float4 p;
            p.x = __expf(e.x - mx.x);
            p.y = __expf(e.y - mx.y);
            p.z = __expf(e.z - mx.z);
            p.w = __expf(e.w - mx.w);
            ((float4*)sE[wip])[j] = p;
            sp.x += p.x; sp.y += p.y; sp.z += p.z; sp.w += p.w;
        }
#pragma unroll
        for (int o = 16; o >= 1; o >>= 1) {
            sp.x += __shfl_xor_sync(0xffffffffu, sp.x, o);
            sp.y += __shfl_xor_sync(0xffffffffu, sp.y, o);
            sp.z += __shfl_xor_sync(0xffffffffu, sp.z, o);
            sp.w += __shfl_xor_sync(0xffffffffu, sp.w, o);
        }
        s = head == 0 ? sp.x : head == 1 ? sp.y : head == 2 ? sp.z : sp.w;
        __syncwarp();
        const float* hl = h + lane * 4;
        int j = 0;
        for (; j + 4 <= len; j += 4) {
            int s0 = sS[wip][j], s1 = sS[wip][j + 1];
            int s2 = sS[wip][j + 2], s3 = sS[wip][j + 3];
            float p0 = sE[wip][(j + 0) * 4 + head];
            float p1 = sE[wip][(j + 1) * 4 + head];
            float p2 = sE[wip][(j + 2) * 4 + head];
            float p3 = sE[wip][(j + 3) * 4 + head];
            float4 h0 = *(const float4*)(hl + (long)s0 * 128);
            float4 h1 = *(const float4*)(hl + (long)s1 * 128);
            float4 h2 = *(const float4*)(hl + (long)s2 * 128);
            float4 h3 = *(const float4*)(hl + (long)s3 * 128);
            acc.x += p0 * h0.x + p1 * h1.x + p2 * h2.x + p3 * h3.x;
            acc.y += p0 * h0.y + p1 * h1.y + p2 * h2.y + p3 * h3.y;
            acc.z += p0 * h0.z + p1 * h1.z + p2 * h2.z + p3 * h3.z;
            acc.w += p0 * h0.w + p1 * h1.w + p2 * h2.w + p3 * h3.w;
        }
        for (; j < len; j++) {
            int s0 = sS[wip][j];
            float p0 = sE[wip][j * 4 + head];
            float4 h0 = *(const float4*)(hl + (long)s0 * 128);
            acc.x += p0 * h0.x;
            acc.y += p0 * h0.y;
            acc.z += p0 * h0.z;
            acc.w += p0 * h0.w;
        }
    } else {
        float ad = head == 0 ? ad4.x : head == 1 ? ad4.y : head == 2 ? ad4.z : ad4.w;
        float m = -1e30f;
        for (int i = beg; i < beg + len; ++i) {
            int src = g_csr[i];
            float e = g_as1[src * 4 + head] + ad;
            e = e > 0.f ? e : 0.2f * e;
            float4 hv = *(const float4*)(h + (long)src * 128 + lane * 4);
            float mn = fmaxf(m, e);
            float sc = __expf(m - mn);
            float p = __expf(e - mn);
            s = s * sc + p;
            acc.x = acc.x * sc + p * hv.x;
            acc.y = acc.y * sc + p * hv.y;
            acc.z = acc.z * sc + p * hv.z;
            acc.w = acc.w * sc + p * hv.w;
            m = mn;
        }
    }
    float inv = 1.f / (s + 1e-16f);
    float4 b = *(const float4*)(bias + lane * 4);
    float4 o;
    o.x = acc.x * inv + b.x;
    o.y = acc.y * inv + b.y;
    o.z = acc.z * inv + b.z;
    o.w = acc.w * inv + b.w;
    o.x = o.x > 0.f ? o.x : (__expf(o.x) - 1.f);
    o.y = o.y > 0.f ? o.y : (__expf(o.y) - 1.f);
    o.z = o.z > 0.f ? o.z : (__expf(o.z) - 1.f);
    o.w = o.w > 0.f ? o.w : (__expf(o.w) - 1.f);
    *(float4*)(out + (long)w * 128 + lane * 4) = o;
}

__global__ void __launch_bounds__(256) k_agg2(const float* __restrict__ h,
                                              const float* __restrict__ bias,
                                              float* __restrict__ out, int n) {
    __shared__ float sE[8][CAP2];
    __shared__ int sS[8][CAP2];
    int w = (blockIdx.x * blockDim.x + threadIdx.x) >> 5;
    if (w >= n) return;
    int wip = threadIdx.x >> 5;
    int lane = threadIdx.x & 31;
    float ad = g_ad2[w];
    int beg = g_off[w];
    int len = g_off[w + 1] - beg;

    float s = 0.f;
    float2 acc = make_float2(0.f, 0.f);

    if (len <= CAP2) {
        float mx = -1e30f;
        for (int j = lane; j < len; j += 32) {
            int src = g_csr[beg + j];
            sS[wip][j] = src;
            float e = g_as2[src] + ad;
            e = e > 0.f ? e : 0.2f * e;
            sE[wip][j] = e;
            mx = fmaxf(mx, e);
        }
#pragma unroll
        for (int o = 16; o >= 1; o >>= 1)
            mx = fmaxf(mx, __shfl_xor_sync(0xffffffffu, mx, o));
        float sp = 0.f;
        for (int j = lane; j < len; j += 32) {
            float p = __expf(sE[wip][j] - mx);
            sE[wip][j] = p;
            sp += p;
        }
#pragma unroll
        for (int o = 16; o >= 1; o >>= 1)
            sp += __shfl_xor_sync(0xffffffffu, sp, o);
        s = sp;
        __syncwarp();
        const float* hl = h + lane * 2;
        int j = 0;
        for (; j + 4 <= len; j += 4) {
            int s0 = sS[wip][j], s1 = sS[wip][j + 1];
            int s2 = sS[wip][j + 2], s3 = sS[wip][j + 3];
            float p0 = sE[wip][j], p1 = sE[wip][j + 1];
            float p2 = sE[wip][j + 2], p3 = sE[wip][j + 3];
            float2 h0 = *(const float2*)(hl + (long)s0 * 64);
            float2 h1 = *(const float2*)(hl + (long)s1 * 64);
            float2 h2 = *(const float2*)(hl + (long)s2 * 64);
            float2 h3 = *(const float2*)(hl + (long)s3 * 64);
            acc.x += p0 * h0.x + p1 * h1.x + p2 * h2.x + p3 * h3.x;
            acc.y += p0 * h0.y + p1 * h1.y + p2 * h2.y + p3 * h3.y;
        }
        for (; j < len; j++) {
            int s0 = sS[wip][j];
            float p0 = sE[wip][j];
            float2 h0 = *(const float2*)(hl + (long)s0 * 64);
            acc.x += p0 * h0.x;
            acc.y += p0 * h0.y;
        }
    } else {
        float m = -1e30f;
        for (int i = beg; i < beg + len; ++i) {
            int src = g_csr[i];
            float e = g_as2[src] + ad;
            e = e > 0.f ? e : 0.2f * e;
            float2 hv = *(const float2*)(h + (long)src * 64 + lane * 2);
            float mn = fmaxf(m, e);
            float sc = __expf(m - mn);
            float p = __expf(e - mn);
            s = s * sc + p;
            acc.x = acc.x * sc + p * hv.x;
            acc.y = acc.y * sc + p * hv.y;
            m = mn;
        }
    }
    float inv = 1.f / (s + 1e-16f);
    float2 b = *(const float2*)(bias + lane * 2);
    float2 o;
    o.x = acc.x * inv + b.x;
    o.y = acc.y * inv + b.y;
    *(float2*)(out + (long)w * 64 + lane * 2) = o;
    if (lane == 0) g_cnt[w] = 0;   // reset counts for the next launch
}

// ---------------------------------------------------------------------------

extern "C" void kernel_launch(void* const* d_in, const int* in_sizes, int n_in,
                              void* d_out, int out_size) {
    const float* x = (const float*)d_in[0];
    const int* ei = (const int*)d_in[1];   // int32
    const float* W1 = (const float*)d_in[2];
    const float* att_s1 = (const float*)d_in[3];
    const float* att_d1 = (const float*)d_in[4];
    const float* b1 = (const float*)d_in[5];
    const float* W2 = (const float*)d_in[6];
    const float* att_s2 = (const float*)d_in[7];
    const float* att_d2 = (const float*)d_in[8];
    const float* b2 = (const float*)d_in[9];
    float* out = (float*)d_out;

    const int N = in_sizes[0] / 128;
    const int E = in_sizes[1] / 2;
    const int* src = ei;
    const int* dst = ei + E;

    const int warpBlocks = (N * 32 + 255) / 256;

    // k_att1 at my slot 4 = the ncu-profiled launch this round.
    k_sgemm<128, 8><<<(N + 127) / 128, 256>>>(x, W1, g_h1, N);   // 1
    k_count<<<(E + 255) / 256, 256>>>(dst, E, N);                // 2
    k_scan<<<1, 1024>>>(N);                                      // 3
    k_att1<<<warpBlocks, 256>>>(g_h1, att_s1, att_d1, N);        // 4 *profiled*
    k_selfloop<<<(N + 255) / 256, 256>>>(N);                     // 5
    k_fill<<<(E + 255) / 256, 256>>>(src, dst, E, N);            // 6
    k_agg1<<<warpBlocks, 256>>>(g_h1, b1, g_out1, N);            // 7
    k_sgemm<64, 4><<<(N + 127) / 128, 256>>>(g_out1, W2, g_h2, N); // 8
    k_att2<<<warpBlocks, 256>>>(g_h2, att_s2, att_d2, N);        // 9
    k_agg2<<<warpBlocks, 256>>>(g_h2, b2, out, N);               // 10
}